// round 1
// baseline (speedup 1.0000x reference)
#include <cuda_runtime.h>

// Problem shapes (fixed by reference): L=4, B=8, C=256, H=64, W=64
#define LN 4
#define BN 8
#define CN 256
#define HW 4096                 // 64*64, contiguous innermost per (l,b,c)
#define SLABS (LN * BN * CN)    // 8192

// Scratch (no device allocation allowed)
__device__ float g_gap[SLABS];
__device__ float g_attn[SLABS];

// ---------------------------------------------------------------------------
// Kernel 1: GAP — one block per (l,b,c) slab of 4096 contiguous floats.
// 256 threads, 4 x float4 per thread.
// ---------------------------------------------------------------------------
__global__ __launch_bounds__(256) void gap_kernel(const float* __restrict__ in) {
    const int slab = blockIdx.x;
    const float4* p = reinterpret_cast<const float4*>(in + (size_t)slab * HW);
    const int tid = threadIdx.x;

    float s = 0.0f;
#pragma unroll
    for (int i = 0; i < 4; ++i) {
        float4 v = p[tid + i * 256];
        s += (v.x + v.y) + (v.z + v.w);
    }

    // warp reduce
#pragma unroll
    for (int off = 16; off > 0; off >>= 1)
        s += __shfl_down_sync(0xffffffffu, s, off);

    __shared__ float warp_s[8];
    if ((tid & 31) == 0) warp_s[tid >> 5] = s;
    __syncthreads();
    if (tid < 8) {
        float t = warp_s[tid];
#pragma unroll
        for (int off = 4; off > 0; off >>= 1)
            t += __shfl_down_sync(0xffu, t, off);
        if (tid == 0) g_gap[slab] = t * (1.0f / (float)HW);
    }
}

// ---------------------------------------------------------------------------
// Kernel 2: scores + softmax-over-L.
// Grid = B (8 blocks), block = 256 threads (thread = output channel d).
// scores[l,b,d] = sum_c gap[l,b,c] * W[d,c]; attn = softmax over l.
// ---------------------------------------------------------------------------
__global__ __launch_bounds__(256) void attn_kernel(const float* __restrict__ Wlin) {
    const int b = blockIdx.x;
    const int d = threadIdx.x;

    __shared__ float g[LN][CN];
#pragma unroll
    for (int l = 0; l < LN; ++l)
        g[l][d] = g_gap[(l * BN + b) * CN + d];
    __syncthreads();

    const float4* wrow = reinterpret_cast<const float4*>(Wlin + (size_t)d * CN);
    float sc[LN] = {0.f, 0.f, 0.f, 0.f};
#pragma unroll 4
    for (int c4 = 0; c4 < CN / 4; ++c4) {
        float4 w = __ldg(&wrow[c4]);
        int c = c4 * 4;
#pragma unroll
        for (int l = 0; l < LN; ++l) {
            sc[l] += g[l][c + 0] * w.x;
            sc[l] += g[l][c + 1] * w.y;
            sc[l] += g[l][c + 2] * w.z;
            sc[l] += g[l][c + 3] * w.w;
        }
    }

    float m = sc[0];
#pragma unroll
    for (int l = 1; l < LN; ++l) m = fmaxf(m, sc[l]);
    float e[LN], sum = 0.f;
#pragma unroll
    for (int l = 0; l < LN; ++l) { e[l] = __expf(sc[l] - m); sum += e[l]; }
    float inv = 1.0f / sum;
#pragma unroll
    for (int l = 0; l < LN; ++l)
        g_attn[(l * BN + b) * CN + d] = e[l] * inv;
}

// ---------------------------------------------------------------------------
// Kernel 3: out = in * attn[l,b,c] broadcast. 1 float4 per thread.
// 4 blocks per slab (4 * 256 * 4 = 4096 floats).
// ---------------------------------------------------------------------------
__global__ __launch_bounds__(256) void scale_kernel(const float* __restrict__ in,
                                                    float* __restrict__ out) {
    const int blk = blockIdx.x;
    const int slab = blk >> 2;
    const float a = __ldg(&g_attn[slab]);
    const size_t i4 = (size_t)blk * 256 + threadIdx.x;   // in float4 units
    float4 v = reinterpret_cast<const float4*>(in)[i4];
    v.x *= a; v.y *= a; v.z *= a; v.w *= a;
    reinterpret_cast<float4*>(out)[i4] = v;
}

extern "C" void kernel_launch(void* const* d_in, const int* in_sizes, int n_in,
                              void* d_out, int out_size) {
    const float* in   = (const float*)d_in[0];   // [4,8,256,64,64]
    const float* Wlin = (const float*)d_in[1];   // [256,256]
    float* out = (float*)d_out;

    gap_kernel<<<SLABS, 256>>>(in);
    attn_kernel<<<BN, 256>>>(Wlin);
    scale_kernel<<<SLABS * 4, 256>>>(in, out);
}

// round 2
// speedup vs baseline: 1.1136x; 1.1136x over previous
#include <cuda_runtime.h>

// Problem shapes (fixed by reference): L=4, B=8, C=256, H=64, W=64
#define LN 4
#define BN 8
#define CN 256
#define HW 4096                 // 64*64, contiguous innermost per (l,b,c)
#define SLABS (LN * BN * CN)    // 8192

// Scratch (no device allocation allowed)
__device__ float g_gap[SLABS];
__device__ float g_attn[SLABS];

// ---------------------------------------------------------------------------
// Kernel 1: GAP — one block per (l,b,c) slab of 4096 contiguous floats.
// 256 threads, 4 x float4 per thread. Default caching: we WANT these lines
// resident in L2 so the scale pass can hit them.
// ---------------------------------------------------------------------------
__global__ __launch_bounds__(256) void gap_kernel(const float* __restrict__ in) {
    const int slab = blockIdx.x;
    const float4* p = reinterpret_cast<const float4*>(in + (size_t)slab * HW);
    const int tid = threadIdx.x;

    float s = 0.0f;
#pragma unroll
    for (int i = 0; i < 4; ++i) {
        float4 v = p[tid + i * 256];
        s += (v.x + v.y) + (v.z + v.w);
    }

#pragma unroll
    for (int off = 16; off > 0; off >>= 1)
        s += __shfl_down_sync(0xffffffffu, s, off);

    __shared__ float warp_s[8];
    if ((tid & 31) == 0) warp_s[tid >> 5] = s;
    __syncthreads();
    if (tid < 8) {
        float t = warp_s[tid];
#pragma unroll
        for (int off = 4; off > 0; off >>= 1)
            t += __shfl_down_sync(0xffu, t, off);
        if (tid == 0) g_gap[slab] = t * (1.0f / (float)HW);
    }
}

// ---------------------------------------------------------------------------
// Kernel 2: scores + softmax-over-L.
// Grid = B (8 blocks), block = 256 threads (thread = output channel d).
// ---------------------------------------------------------------------------
__global__ __launch_bounds__(256) void attn_kernel(const float* __restrict__ Wlin) {
    const int b = blockIdx.x;
    const int d = threadIdx.x;

    __shared__ float g[LN][CN];
#pragma unroll
    for (int l = 0; l < LN; ++l)
        g[l][d] = g_gap[(l * BN + b) * CN + d];
    __syncthreads();

    const float4* wrow = reinterpret_cast<const float4*>(Wlin + (size_t)d * CN);
    float sc[LN] = {0.f, 0.f, 0.f, 0.f};
#pragma unroll 4
    for (int c4 = 0; c4 < CN / 4; ++c4) {
        float4 w = __ldg(&wrow[c4]);
        int c = c4 * 4;
#pragma unroll
        for (int l = 0; l < LN; ++l) {
            sc[l] += g[l][c + 0] * w.x;
            sc[l] += g[l][c + 1] * w.y;
            sc[l] += g[l][c + 2] * w.z;
            sc[l] += g[l][c + 3] * w.w;
        }
    }

    float m = sc[0];
#pragma unroll
    for (int l = 1; l < LN; ++l) m = fmaxf(m, sc[l]);
    float e[LN], sum = 0.f;
#pragma unroll
    for (int l = 0; l < LN; ++l) { e[l] = __expf(sc[l] - m); sum += e[l]; }
    float inv = 1.0f / sum;
#pragma unroll
    for (int l = 0; l < LN; ++l)
        g_attn[(l * BN + b) * CN + d] = e[l] * inv;
}

// ---------------------------------------------------------------------------
// Kernel 3: out = in * attn[l,b,c], REVERSE slab order.
// gap_kernel streamed slabs 0..8191, so L2 holds the tail (~126 MB of the
// 134 MB input = slabs ~500..8191). Reading in reverse order consumes the
// hottest lines first. __ldcs: input line is dead after this read.
// __stcs: output stores evict-first so they don't displace cached input.
// ---------------------------------------------------------------------------
__global__ __launch_bounds__(256) void scale_kernel(const float* __restrict__ in,
                                                    float* __restrict__ out) {
    const int blk  = (SLABS * 4 - 1) - blockIdx.x;   // reverse order
    const int slab = blk >> 2;
    const float a = __ldg(&g_attn[slab]);
    const size_t i4 = (size_t)blk * 256 + threadIdx.x;   // in float4 units
    float4 v = __ldcs(reinterpret_cast<const float4*>(in) + i4);
    v.x *= a; v.y *= a; v.z *= a; v.w *= a;
    __stcs(reinterpret_cast<float4*>(out) + i4, v);
}

extern "C" void kernel_launch(void* const* d_in, const int* in_sizes, int n_in,
                              void* d_out, int out_size) {
    const float* in   = (const float*)d_in[0];   // [4,8,256,64,64]
    const float* Wlin = (const float*)d_in[1];   // [256,256]
    float* out = (float*)d_out;

    gap_kernel<<<SLABS, 256>>>(in);
    attn_kernel<<<BN, 256>>>(Wlin);
    scale_kernel<<<SLABS * 4, 256>>>(in, out);
}